// round 12
// baseline (speedup 1.0000x reference)
#include <cuda_runtime.h>
#include <cuda_fp16.h>
#include <cstdint>

#define BATCH 8
#define CCH   128
#define HH    128
#define WW    256
#define KS    9
#define NTOT  (BATCH*CCH*HH*WW)

__device__ float g_tmp[NTOT];                        // transposed scratch
// halo buffers: [b][tile][side][parity][split][4 rows][128 ci] fp16
__device__ __align__(16) __half g_halo[BATCH][8][2][2][2][4][128];
// per-(pass,b,tile,half) step flags, padded 32B
__device__ unsigned g_flags[4][BATCH][8][2][8];

__device__ __forceinline__ unsigned ld_acq(const unsigned* p) {
    unsigned v;
    asm volatile("ld.acquire.gpu.global.u32 %0, [%1];" : "=r"(v) : "l"(p) : "memory");
    return v;
}
__device__ __forceinline__ void st_rel(unsigned* p, unsigned v) {
    asm volatile("st.release.gpu.global.u32 [%0], %1;" :: "l"(p), "r"(v) : "memory");
}
__device__ __forceinline__ uint32_t smem_u32(const void* p) {
    uint32_t a;
    asm("{ .reg .u64 t; cvta.to.shared.u64 t, %1; cvt.u32.u64 %0, t; }"
        : "=r"(a) : "l"(p));
    return a;
}
__device__ __forceinline__ uint32_t mapa_peer(uint32_t addr, uint32_t rank) {
    uint32_t r;
    asm("mapa.shared::cluster.u32 %0, %1, %2;" : "=r"(r) : "r"(addr), "r"(rank));
    return r;
}
__device__ __forceinline__ void st_dsmem(uint32_t addr, uint32_t v) {
    asm volatile("st.shared::cluster.u32 [%0], %1;" :: "r"(addr), "r"(v) : "memory");
}
__device__ __forceinline__ void sts32(uint32_t addr, uint32_t v) {
    asm volatile("st.shared.u32 [%0], %1;" :: "r"(addr), "r"(v) : "memory");
}
__device__ __forceinline__ void cluster_sync() {
    asm volatile("barrier.cluster.arrive.aligned;" ::: "memory");
    asm volatile("barrier.cluster.wait.aligned;" ::: "memory");
}
__device__ __forceinline__ uint32_t ctarank() {
    uint32_t r; asm("mov.u32 %0, %%cluster_ctarank;" : "=r"(r)); return r;
}
__device__ __forceinline__ void cp16(uint32_t d, const void* s) {
    asm volatile("cp.async.cg.shared.global [%0], [%1], 16;" :: "r"(d), "l"(s));
}
__device__ __forceinline__ void ldsm4(uint32_t addr, uint32_t& r0, uint32_t& r1,
                                      uint32_t& r2, uint32_t& r3) {
    asm volatile("ldmatrix.sync.aligned.m8n8.x4.shared.b16 {%0,%1,%2,%3}, [%4];"
                 : "=r"(r0), "=r"(r1), "=r"(r2), "=r"(r3) : "r"(addr));
}
__device__ __forceinline__ void ldsm2(uint32_t addr, uint32_t& r0, uint32_t& r1) {
    asm volatile("ldmatrix.sync.aligned.m8n8.x2.shared.b16 {%0,%1}, [%2];"
                 : "=r"(r0), "=r"(r1) : "r"(addr));
}
__device__ __forceinline__ void mma_f16(float* c, const uint32_t* a,
                                        uint32_t b0, uint32_t b1) {
    asm volatile(
        "mma.sync.aligned.m16n8k16.row.col.f32.f16.f16.f32 "
        "{%0,%1,%2,%3}, {%4,%5,%6,%7}, {%8,%9}, {%0,%1,%2,%3};"
        : "+f"(c[0]), "+f"(c[1]), "+f"(c[2]), "+f"(c[3])
        : "r"(a[0]), "r"(a[1]), "r"(a[2]), "r"(a[3]), "r"(b0), "r"(b1));
}
__device__ __forceinline__ uint32_t h2u(__half a, __half b) {
    __half2 t = __halves2half2(a, b);
    return *reinterpret_cast<uint32_t*>(&t);
}

// ---------------------------------------------------------------------------
// Cluster(2) persistent pass kernel with two-phase MMA.
// CTA = (co-half 64, l-tile M, batch); co-halves of a tile form a cluster.
// Carry stays in smem (own: direct; sibling: DSMEM + cluster_sync; +-4 column
// l-halos: global buffers + flags). Per step: interior-tap MMAs issue BEFORE
// the l-neighbor flag wait (hides flag detect + halo L2 RT); buf STG deferred
// until after the flag release (off the inter-CTA critical path).
// fp16 weights, 2-term fp16 split on carry (A).
// out[l,co] = x + relu( sum_{ci,k} w[co,ci,k]*prev[ci,l+k-4] )
// ---------------------------------------------------------------------------
template<int S, int L, int M>
__global__ void __cluster_dims__(2, 1, 1) __launch_bounds__(256, 1)
pass_kernel(float* __restrict__ buf, const float* __restrict__ wgt,
            unsigned* __restrict__ flags, int reverse)
{
    constexpr int ROWS   = M + 8;
    constexpr int AST    = 136;                  // A/W row stride (halfs)
    constexpr int ASPLIT = ROWS * AST * 2;       // bytes per (parity,split)
    constexpr int SM_W   = 4 * ASPLIT;
    constexpr int W_SZ   = KS * 64 * AST * 2;
    constexpr int SM_X   = SM_W + W_SZ;
    constexpr int XST    = M + 4;                // x stage row stride (floats)
    constexpr int NT     = M / 16;               // n8-tiles per warp (2 V, 1 H)
    constexpr int COW    = NT * 8;               // co per warp

    extern __shared__ char sm[];
    const uint32_t smb = smem_u32(sm);
    float* xs = (float*)(sm + SM_X);

    const int tid  = threadIdx.x;
    const int wid  = tid >> 5;
    const int lane = tid & 31;
    const int half = blockIdx.x;                 // cluster rank
    const int tile = blockIdx.y;
    const int b    = blockIdx.z;
    const int l0   = tile * M;
    const int co0h = half * 64;
    const uint32_t peer = 1u - ctarank();
    const uint32_t rbase = mapa_peer(smb, peer);

    float* base = buf + (size_t)b * CCH * S * L;
    unsigned* fown = flags + (((b * 8 + tile) * 2 + half) * 8);
    unsigned* pollf[4];
    pollf[0] = (tile > 0) ? flags + (((b * 8 + tile - 1) * 2 + 0) * 8) : nullptr;
    pollf[1] = (tile > 0) ? flags + (((b * 8 + tile - 1) * 2 + 1) * 8) : nullptr;
    pollf[2] = (tile < 7) ? flags + (((b * 8 + tile + 1) * 2 + 0) * 8) : nullptr;
    pollf[3] = (tile < 7) ? flags + (((b * 8 + tile + 1) * 2 + 1) * 8) : nullptr;

    // ---- resident weights: wgt[co][ci][k] -> W[tap*64+co_local][ci] fp16 ----
    {
        __half* W = (__half*)(sm + SM_W);
        for (int idx = tid; idx < 64 * CCH * KS; idx += 256) {
            int co = idx / (CCH * KS);
            int r  = idx % (CCH * KS);
            int ci = r / KS;
            int k  = r % KS;
            float v = wgt[(size_t)(co0h + co) * CCH * KS + (size_t)ci * KS + k];
            W[(k * 64 + co) * AST + ci] = __float2half_rn(v);
        }
    }
    // ---- zero A (both parities), then fill A[par0] with x row s0 window ----
    for (int idx = tid; idx < 4 * ASPLIT / 4; idx += 256)
        ((uint32_t*)sm)[idx] = 0u;
    __syncthreads();
    {
        const int s0 = reverse ? (S - 1) : 0;
        const float* src = base + (size_t)s0 * L;
        __half* A_hi = (__half*)sm;              // parity0, split hi
        __half* A_lo = (__half*)(sm + ASPLIT);   // parity0, split lo
        for (int idx = tid; idx < CCH * ROWS; idx += 256) {
            int ci = idx / ROWS;
            int r  = idx % ROWS;
            int gl = l0 - 4 + r;
            float v = (gl >= 0 && gl < L) ? src[(size_t)ci * S * L + gl] : 0.0f;
            __half hi = __float2half_rn(v);
            __half lo = __float2half_rn(v - __half2float(hi));
            A_hi[r * AST + ci] = hi;
            A_lo[r * AST + ci] = lo;
        }
    }
    __syncthreads();

    // warp tiling: V (NT=2): g=wid>>1 (co16), mt=wid&1. H (NT=1): g=wid, mt=0.
    const int g  = (NT == 2) ? (wid >> 1) : wid;
    const int mt = (NT == 2) ? (wid & 1) : 0;
    const int lt    = lane >> 3;
    const int lrow  = (lane & 7) + ((lt & 1) << 3);
    const int lk    = (lt >> 1) << 3;
    const int l2row = lane & 7;
    const int l2k   = ((lane >> 3) & 1) << 3;
    const int r4    = lane >> 2;
    const int cp2   = (lane & 3) * 2;
    const uint32_t smW = smb + SM_W;

    for (int i = 1; i < S; ++i) {
        const int s_cur = reverse ? (S - 1 - i) : i;
        const int pprev = (i - 1) & 1;
        const int pcur  = i & 1;

        // ---- x row prefetch (group committed now; waited before phase 2) ----
        {
            const float* xsrc = base + (size_t)s_cur * L + l0;
#pragma unroll
            for (int t = 0; t < (64 * (M / 4)) / 256; ++t) {
                int idx = tid + t * 256;
                int co  = idx / (M / 4);
                int lq  = idx % (M / 4);
                cp16(smb + SM_X + (uint32_t)(co * XST + lq * 4) * 4,
                     xsrc + (size_t)(co0h + co) * S * L + lq * 4);
            }
            asm volatile("cp.async.commit_group;" ::: "memory");
        }

        float acc[NT][4];
#pragma unroll
        for (int nt = 0; nt < NT; ++nt)
#pragma unroll
            for (int e = 0; e < 4; ++e) acc[nt][e] = 0.0f;

        const uint32_t aB0 = smb + (uint32_t)(pprev * 2 + 0) * ASPLIT;
        const uint32_t aB1 = smb + (uint32_t)(pprev * 2 + 1) * ASPLIT;

        auto mma_taps = [&](int tap_base, int ntaps) {
            for (int tt = 0; tt < ntaps; ++tt) {
                const int tap = tap_base + tt;
#pragma unroll
                for (int kc = 0; kc < 8; ++kc) {
                    uint32_t b0, b1, b2, b3;
                    if constexpr (NT == 2) {
                        ldsm4(smW + (uint32_t)(((tap * 64 + g * 16 + lrow) * AST
                                                + kc * 16 + lk) * 2), b0, b1, b2, b3);
                    } else {
                        ldsm2(smW + (uint32_t)(((tap * 64 + g * 8 + l2row) * AST
                                                + kc * 16 + l2k) * 2), b0, b1);
                    }
                    const uint32_t arow = (uint32_t)(((mt * 16 + tap + lrow) * AST
                                                      + kc * 16 + lk) * 2);
                    uint32_t a[4];
                    ldsm4(aB0 + arow, a[0], a[1], a[2], a[3]);
                    if constexpr (NT == 2) {
                        mma_f16(acc[0], a, b0, b2);
                        mma_f16(acc[1], a, b1, b3);
                    } else {
                        mma_f16(acc[0], a, b0, b1);
                    }
                    ldsm4(aB1 + arow, a[0], a[1], a[2], a[3]);
                    if constexpr (NT == 2) {
                        mma_f16(acc[0], a, b0, b2);
                        mma_f16(acc[1], a, b1, b3);
                    } else {
                        mma_f16(acc[0], a, b0, b1);
                    }
                }
            }
        };

        // ---- phase 1: interior taps (no l-halo rows touched) ----
        if constexpr (NT == 2) {
            mma_taps((mt == 0) ? 4 : 0, 5);
        } else {
            mma_taps(4, 1);
        }

        // ---- wait l-neighbors, pull 4-col halos into A[pprev] ----
        if (i >= 2) {
            if (tid < 4) {
                unsigned* f = pollf[tid];
                if (f) while (ld_acq(f) < (unsigned)(i - 1)) __nanosleep(16);
            }
            __syncthreads();
            const int s     = tid >> 7;            // 0 = left, 1 = right
            const int split = (tid >> 6) & 1;
            const int r     = (tid >> 4) & 3;
            const int c     = tid & 15;
            const bool have = (s == 0) ? (tile > 0) : (tile < 7);
            if (have) {
                const __half* src = &g_halo[b][s == 0 ? tile - 1 : tile + 1]
                                           [s == 0 ? 1 : 0][pprev][split][r][c * 8];
                uint32_t dst = smb + (uint32_t)(pprev * 2 + split) * ASPLIT
                             + (uint32_t)(((s == 0 ? r : M + 4 + r) * AST + c * 8) * 2);
                cp16(dst, src);
            }
        }
        asm volatile("cp.async.commit_group;" ::: "memory");
        asm volatile("cp.async.wait_group 0;" ::: "memory");
        __syncthreads();

        // ---- phase 2: halo taps ----
        if constexpr (NT == 2) {
            mma_taps((mt == 0) ? 0 : 5, 4);
        } else {
            mma_taps(0, 4);
            mma_taps(5, 4);
        }

        // ---- epilogue part 1: o = x + relu(acc); smem A, sibling A, halo ----
        float osav[NT][2][2];
        {
            const uint32_t oHi = (uint32_t)(pcur * 2 + 0) * ASPLIT;
            const uint32_t oLo = (uint32_t)(pcur * 2 + 1) * ASPLIT;
#pragma unroll
            for (int nt = 0; nt < NT; ++nt) {
#pragma unroll
                for (int h2 = 0; h2 < 2; ++h2) {
                    const int ll = mt * 16 + r4 + h2 * 8;
                    const int co = g * COW + nt * 8 + cp2;
                    float o0 = xs[co * XST + ll]
                             + fmaxf(acc[nt][h2 * 2 + 0], 0.0f);
                    float o1 = xs[(co + 1) * XST + ll]
                             + fmaxf(acc[nt][h2 * 2 + 1], 0.0f);
                    osav[nt][h2][0] = o0;
                    osav[nt][h2][1] = o1;
                    __half h0 = __float2half_rn(o0);
                    __half h1 = __float2half_rn(o1);
                    uint32_t hi2 = h2u(h0, h1);
                    uint32_t lo2 = h2u(__float2half_rn(o0 - __half2float(h0)),
                                       __float2half_rn(o1 - __half2float(h1)));
                    const uint32_t aoff =
                        (uint32_t)(((ll + 4) * AST + co0h + co) * 2);
                    sts32(smb + oHi + aoff, hi2);
                    sts32(smb + oLo + aoff, lo2);
                    st_dsmem(rbase + oHi + aoff, hi2);
                    st_dsmem(rbase + oLo + aoff, lo2);
                    if (ll < 4) {
                        *(__half2*)&g_halo[b][tile][0][pcur][0][ll][co0h + co] =
                            __halves2half2(h0, h1);
                        *(__half2*)&g_halo[b][tile][0][pcur][1][ll][co0h + co] =
                            *(__half2*)&lo2;
                    }
                    if (ll >= M - 4) {
                        *(__half2*)&g_halo[b][tile][1][pcur][0][ll - (M - 4)][co0h + co] =
                            __halves2half2(h0, h1);
                        *(__half2*)&g_halo[b][tile][1][pcur][1][ll - (M - 4)][co0h + co] =
                            *(__half2*)&lo2;
                    }
                }
            }
        }

        __syncthreads();                      // halo/smem/DSMEM stores issued
        if (i <= S - 2 && tid == 0) st_rel(fown, (unsigned)i);

        // ---- epilogue part 2: deferred buf STG (off critical path) ----
#pragma unroll
        for (int nt = 0; nt < NT; ++nt) {
#pragma unroll
            for (int h2 = 0; h2 < 2; ++h2) {
                const int ll = mt * 16 + r4 + h2 * 8;
                const int co = g * COW + nt * 8 + cp2;
                base[((size_t)(co0h + co) * S + s_cur) * L + l0 + ll]     = osav[nt][h2][0];
                base[((size_t)(co0h + co + 1) * S + s_cur) * L + l0 + ll] = osav[nt][h2][1];
            }
        }

        cluster_sync();                       // DSMEM A[pcur] visible to sibling
    }
}

// ---------------------------------------------------------------------------
// Transpose [P, A, B] -> [P, B, A]
// ---------------------------------------------------------------------------
__global__ void transpose_kernel(const float* __restrict__ in,
                                 float* __restrict__ out, int A, int B)
{
    __shared__ float tile[32][33];
    const size_t p = blockIdx.z;
    const int b0 = blockIdx.x * 32;
    const int a0 = blockIdx.y * 32;
    const int tx = threadIdx.x, ty = threadIdx.y;
    const float* ip = in  + p * (size_t)A * B;
    float*       op = out + p * (size_t)A * B;
#pragma unroll
    for (int i = ty; i < 32; i += 8)
        tile[i][tx] = ip[(size_t)(a0+i)*B + (b0+tx)];
    __syncthreads();
#pragma unroll
    for (int i = ty; i < 32; i += 8)
        op[(size_t)(b0+i)*A + (a0+tx)] = tile[tx][i];
}

// Vertical: [B,C,S=H=128,L=W=256], M=32 (8 tiles). Horizontal: S=256,L=128, M=16.
#define PASSV pass_kernel<128,256,32>
#define PASSH pass_kernel<256,128,16>

static constexpr int SMEM_V = 4*(40*136*2) + KS*64*136*2 + 64*36*4;  // 209408
static constexpr int SMEM_H = 4*(24*136*2) + KS*64*136*2 + 64*20*4;  // 187904

extern "C" void kernel_launch(void* const* d_in, const int* in_sizes, int n_in,
                              void* d_out, int out_size)
{
    const float* x    = (const float*)d_in[0];
    const float* w_ud = (const float*)d_in[1];
    const float* w_du = (const float*)d_in[2];
    const float* w_lr = (const float*)d_in[3];
    const float* w_rl = (const float*)d_in[4];
    float* buf = (float*)d_out;

    float* tbuf = nullptr;
    cudaGetSymbolAddress((void**)&tbuf, g_tmp);
    unsigned* flags = nullptr;
    cudaGetSymbolAddress((void**)&flags, g_flags);

    cudaFuncSetAttribute(PASSV, cudaFuncAttributeMaxDynamicSharedMemorySize, SMEM_V);
    cudaFuncSetAttribute(PASSH, cudaFuncAttributeMaxDynamicSharedMemorySize, SMEM_H);

    cudaMemsetAsync(flags, 0, 4 * BATCH * 8 * 2 * 8 * sizeof(unsigned), 0);
    cudaMemcpyAsync(buf, x, (size_t)NTOT * sizeof(float),
                    cudaMemcpyDeviceToDevice, 0);

    const unsigned PSTRIDE = BATCH * 8 * 2 * 8;

    dim3 g(2, 8, BATCH);   // 128 CTAs = 64 clusters of 2, all resident
    PASSV<<<g, 256, SMEM_V>>>(buf, w_ud, flags + 0*PSTRIDE, 0);
    PASSV<<<g, 256, SMEM_V>>>(buf, w_du, flags + 1*PSTRIDE, 1);

    transpose_kernel<<<dim3(WW/32, HH/32, BATCH*CCH), dim3(32,8)>>>(buf, tbuf, HH, WW);

    PASSH<<<g, 256, SMEM_H>>>(tbuf, w_lr, flags + 2*PSTRIDE, 0);
    PASSH<<<g, 256, SMEM_H>>>(tbuf, w_rl, flags + 3*PSTRIDE, 1);

    transpose_kernel<<<dim3(HH/32, WW/32, BATCH*CCH), dim3(32,8)>>>(tbuf, buf, WW, HH);
}

// round 13
// speedup vs baseline: 1.3102x; 1.3102x over previous
#include <cuda_runtime.h>
#include <cuda_fp16.h>
#include <cstdint>

#define BATCH 8
#define CCH   128
#define HH    128
#define WW    256
#define KS    9
#define NTOT  (BATCH*CCH*HH*WW)

__device__ float g_tmp[NTOT];                        // transposed scratch
// halo buffers: [b][tile][side][parity][4 rows][128 ci] fp16
__device__ __align__(16) __half g_halo[BATCH][8][2][2][4][128];
// per-(pass,b,tile,half) step flags, padded 32B
__device__ unsigned g_flags[4][BATCH][8][2][8];

__device__ __forceinline__ unsigned ld_acq(const unsigned* p) {
    unsigned v;
    asm volatile("ld.acquire.gpu.global.u32 %0, [%1];" : "=r"(v) : "l"(p) : "memory");
    return v;
}
__device__ __forceinline__ void st_rel(unsigned* p, unsigned v) {
    asm volatile("st.release.gpu.global.u32 [%0], %1;" :: "l"(p), "r"(v) : "memory");
}
__device__ __forceinline__ uint32_t smem_u32(const void* p) {
    uint32_t a;
    asm("{ .reg .u64 t; cvta.to.shared.u64 t, %1; cvt.u32.u64 %0, t; }"
        : "=r"(a) : "l"(p));
    return a;
}
__device__ __forceinline__ uint32_t mapa_peer(uint32_t addr, uint32_t rank) {
    uint32_t r;
    asm("mapa.shared::cluster.u32 %0, %1, %2;" : "=r"(r) : "r"(addr), "r"(rank));
    return r;
}
__device__ __forceinline__ void st_dsmem(uint32_t addr, uint32_t v) {
    asm volatile("st.shared::cluster.u32 [%0], %1;" :: "r"(addr), "r"(v) : "memory");
}
__device__ __forceinline__ void sts32(uint32_t addr, uint32_t v) {
    asm volatile("st.shared.u32 [%0], %1;" :: "r"(addr), "r"(v) : "memory");
}
__device__ __forceinline__ void cluster_sync() {
    asm volatile("barrier.cluster.arrive.aligned;" ::: "memory");
    asm volatile("barrier.cluster.wait.aligned;" ::: "memory");
}
__device__ __forceinline__ uint32_t ctarank() {
    uint32_t r; asm("mov.u32 %0, %%cluster_ctarank;" : "=r"(r)); return r;
}
__device__ __forceinline__ void cp16(uint32_t d, const void* s) {
    asm volatile("cp.async.cg.shared.global [%0], [%1], 16;" :: "r"(d), "l"(s));
}
__device__ __forceinline__ void ldsm4(uint32_t addr, uint32_t& r0, uint32_t& r1,
                                      uint32_t& r2, uint32_t& r3) {
    asm volatile("ldmatrix.sync.aligned.m8n8.x4.shared.b16 {%0,%1,%2,%3}, [%4];"
                 : "=r"(r0), "=r"(r1), "=r"(r2), "=r"(r3) : "r"(addr));
}
__device__ __forceinline__ void ldsm2(uint32_t addr, uint32_t& r0, uint32_t& r1) {
    asm volatile("ldmatrix.sync.aligned.m8n8.x2.shared.b16 {%0,%1}, [%2];"
                 : "=r"(r0), "=r"(r1) : "r"(addr));
}
__device__ __forceinline__ void mma_f16(float* c, const uint32_t* a,
                                        uint32_t b0, uint32_t b1) {
    asm volatile(
        "mma.sync.aligned.m16n8k16.row.col.f32.f16.f16.f32 "
        "{%0,%1,%2,%3}, {%4,%5,%6,%7}, {%8,%9}, {%0,%1,%2,%3};"
        : "+f"(c[0]), "+f"(c[1]), "+f"(c[2]), "+f"(c[3])
        : "r"(a[0]), "r"(a[1]), "r"(a[2]), "r"(a[3]), "r"(b0), "r"(b1));
}
__device__ __forceinline__ uint32_t h2u(__half a, __half b) {
    __half2 t = __halves2half2(a, b);
    return *reinterpret_cast<uint32_t*>(&t);
}

// ---------------------------------------------------------------------------
// Cluster(2) persistent pass kernel, SINGLE-term fp16 (carry + weights fp16).
// CTA = (co-half 64, l-tile M, batch); co-halves of a tile form a cluster.
// Carry stays in smem (own: direct; sibling: DSMEM + cluster_sync; +-4 column
// l-halos: global buffers + flags). Two-phase MMA: interior taps issue before
// the l-neighbor flag wait; buf STG deferred past the flag release.
// out[l,co] = x + relu( sum_{ci,k} w[co,ci,k]*prev[ci,l+k-4] )
// ---------------------------------------------------------------------------
template<int S, int L, int M>
__global__ void __cluster_dims__(2, 1, 1) __launch_bounds__(256, 1)
pass_kernel(float* __restrict__ buf, const float* __restrict__ wgt,
            unsigned* __restrict__ flags, int reverse)
{
    constexpr int ROWS  = M + 8;
    constexpr int AST   = 136;                  // A/W row stride (halfs)
    constexpr int ASIZE = ROWS * AST * 2;       // bytes per parity
    constexpr int SM_W  = 2 * ASIZE;
    constexpr int W_SZ  = KS * 64 * AST * 2;
    constexpr int SM_X  = SM_W + W_SZ;
    constexpr int XST   = M + 4;                // x stage row stride (floats)
    constexpr int NT    = M / 16;               // n8-tiles per warp (2 V, 1 H)
    constexpr int COW   = NT * 8;               // co per warp

    extern __shared__ char sm[];
    const uint32_t smb = smem_u32(sm);
    float* xs = (float*)(sm + SM_X);

    const int tid  = threadIdx.x;
    const int wid  = tid >> 5;
    const int lane = tid & 31;
    const int half = blockIdx.x;                 // cluster rank
    const int tile = blockIdx.y;
    const int b    = blockIdx.z;
    const int l0   = tile * M;
    const int co0h = half * 64;
    const uint32_t peer = 1u - ctarank();
    const uint32_t rbase = mapa_peer(smb, peer);

    float* base = buf + (size_t)b * CCH * S * L;
    unsigned* fown = flags + (((b * 8 + tile) * 2 + half) * 8);
    unsigned* pollf[4];
    pollf[0] = (tile > 0) ? flags + (((b * 8 + tile - 1) * 2 + 0) * 8) : nullptr;
    pollf[1] = (tile > 0) ? flags + (((b * 8 + tile - 1) * 2 + 1) * 8) : nullptr;
    pollf[2] = (tile < 7) ? flags + (((b * 8 + tile + 1) * 2 + 0) * 8) : nullptr;
    pollf[3] = (tile < 7) ? flags + (((b * 8 + tile + 1) * 2 + 1) * 8) : nullptr;

    // ---- resident weights: wgt[co][ci][k] -> W[tap*64+co_local][ci] fp16 ----
    {
        __half* W = (__half*)(sm + SM_W);
        for (int idx = tid; idx < 64 * CCH * KS; idx += 256) {
            int co = idx / (CCH * KS);
            int r  = idx % (CCH * KS);
            int ci = r / KS;
            int k  = r % KS;
            float v = wgt[(size_t)(co0h + co) * CCH * KS + (size_t)ci * KS + k];
            W[(k * 64 + co) * AST + ci] = __float2half_rn(v);
        }
    }
    // ---- zero A (both parities), then fill A[par0] with x row s0 window ----
    for (int idx = tid; idx < 2 * ASIZE / 4; idx += 256)
        ((uint32_t*)sm)[idx] = 0u;
    __syncthreads();
    {
        const int s0 = reverse ? (S - 1) : 0;
        const float* src = base + (size_t)s0 * L;
        __half* A0 = (__half*)sm;                // parity 0
        for (int idx = tid; idx < CCH * ROWS; idx += 256) {
            int ci = idx / ROWS;
            int r  = idx % ROWS;
            int gl = l0 - 4 + r;
            float v = (gl >= 0 && gl < L) ? src[(size_t)ci * S * L + gl] : 0.0f;
            A0[r * AST + ci] = __float2half_rn(v);
        }
    }
    __syncthreads();

    // warp tiling: V (NT=2): g=wid>>1 (co16), mt=wid&1. H (NT=1): g=wid, mt=0.
    const int g  = (NT == 2) ? (wid >> 1) : wid;
    const int mt = (NT == 2) ? (wid & 1) : 0;
    const int lt    = lane >> 3;
    const int lrow  = (lane & 7) + ((lt & 1) << 3);
    const int lk    = (lt >> 1) << 3;
    const int l2row = lane & 7;
    const int l2k   = ((lane >> 3) & 1) << 3;
    const int r4    = lane >> 2;
    const int cp2   = (lane & 3) * 2;
    const uint32_t smW = smb + SM_W;

    for (int i = 1; i < S; ++i) {
        const int s_cur = reverse ? (S - 1 - i) : i;
        const int pprev = (i - 1) & 1;
        const int pcur  = i & 1;

        // ---- x row prefetch (committed now; waited before phase 2) ----
        {
            const float* xsrc = base + (size_t)s_cur * L + l0;
#pragma unroll
            for (int t = 0; t < (64 * (M / 4)) / 256; ++t) {
                int idx = tid + t * 256;
                int co  = idx / (M / 4);
                int lq  = idx % (M / 4);
                cp16(smb + SM_X + (uint32_t)(co * XST + lq * 4) * 4,
                     xsrc + (size_t)(co0h + co) * S * L + lq * 4);
            }
            asm volatile("cp.async.commit_group;" ::: "memory");
        }

        float acc[NT][4];
#pragma unroll
        for (int nt = 0; nt < NT; ++nt)
#pragma unroll
            for (int e = 0; e < 4; ++e) acc[nt][e] = 0.0f;

        const uint32_t aB = smb + (uint32_t)pprev * ASIZE;

        auto mma_taps = [&](int tap_base, int ntaps) {
            for (int tt = 0; tt < ntaps; ++tt) {
                const int tap = tap_base + tt;
#pragma unroll
                for (int kc = 0; kc < 8; ++kc) {
                    uint32_t b0, b1, b2, b3;
                    if constexpr (NT == 2) {
                        ldsm4(smW + (uint32_t)(((tap * 64 + g * 16 + lrow) * AST
                                                + kc * 16 + lk) * 2), b0, b1, b2, b3);
                    } else {
                        ldsm2(smW + (uint32_t)(((tap * 64 + g * 8 + l2row) * AST
                                                + kc * 16 + l2k) * 2), b0, b1);
                    }
                    uint32_t a[4];
                    ldsm4(aB + (uint32_t)(((mt * 16 + tap + lrow) * AST
                                           + kc * 16 + lk) * 2),
                          a[0], a[1], a[2], a[3]);
                    if constexpr (NT == 2) {
                        mma_f16(acc[0], a, b0, b2);
                        mma_f16(acc[1], a, b1, b3);
                    } else {
                        mma_f16(acc[0], a, b0, b1);
                    }
                }
            }
        };

        // ---- phase 1: interior taps (no l-halo rows touched) ----
        if constexpr (NT == 2) {
            mma_taps((mt == 0) ? 4 : 0, 5);
        } else {
            mma_taps(4, 1);
        }

        // ---- wait l-neighbors, pull 4-col halos into A[pprev] ----
        if (i >= 2) {
            if (tid < 4) {
                unsigned* f = pollf[tid];
                if (f) while (ld_acq(f) < (unsigned)(i - 1)) __nanosleep(16);
            }
            __syncthreads();
            if (tid < 128) {
                const int s = tid >> 6;            // 0 = left, 1 = right
                const int r = (tid >> 4) & 3;
                const int c = tid & 15;
                const bool have = (s == 0) ? (tile > 0) : (tile < 7);
                if (have) {
                    const __half* src = &g_halo[b][s == 0 ? tile - 1 : tile + 1]
                                               [s == 0 ? 1 : 0][pprev][r][c * 8];
                    uint32_t dst = smb + (uint32_t)pprev * ASIZE
                                 + (uint32_t)(((s == 0 ? r : M + 4 + r) * AST + c * 8) * 2);
                    cp16(dst, src);
                }
            }
        }
        asm volatile("cp.async.commit_group;" ::: "memory");
        asm volatile("cp.async.wait_group 0;" ::: "memory");
        __syncthreads();

        // ---- phase 2: halo taps ----
        if constexpr (NT == 2) {
            mma_taps((mt == 0) ? 0 : 5, 4);
        } else {
            mma_taps(0, 4);
            mma_taps(5, 4);
        }

        // ---- epilogue part 1: o = x + relu(acc); smem A, sibling A, halo ----
        float osav[NT][2][2];
        {
            const uint32_t oA = (uint32_t)pcur * ASIZE;
#pragma unroll
            for (int nt = 0; nt < NT; ++nt) {
#pragma unroll
                for (int h2 = 0; h2 < 2; ++h2) {
                    const int ll = mt * 16 + r4 + h2 * 8;
                    const int co = g * COW + nt * 8 + cp2;
                    float o0 = xs[co * XST + ll]
                             + fmaxf(acc[nt][h2 * 2 + 0], 0.0f);
                    float o1 = xs[(co + 1) * XST + ll]
                             + fmaxf(acc[nt][h2 * 2 + 1], 0.0f);
                    osav[nt][h2][0] = o0;
                    osav[nt][h2][1] = o1;
                    uint32_t hi2 = h2u(__float2half_rn(o0), __float2half_rn(o1));
                    const uint32_t aoff =
                        (uint32_t)(((ll + 4) * AST + co0h + co) * 2);
                    sts32(smb + oA + aoff, hi2);
                    st_dsmem(rbase + oA + aoff, hi2);
                    if (ll < 4)
                        *(uint32_t*)&g_halo[b][tile][0][pcur][ll][co0h + co] = hi2;
                    if (ll >= M - 4)
                        *(uint32_t*)&g_halo[b][tile][1][pcur][ll - (M - 4)][co0h + co] = hi2;
                }
            }
        }

        __syncthreads();                      // halo/smem/DSMEM stores issued
        if (i <= S - 2 && tid == 0) st_rel(fown, (unsigned)i);

        // ---- epilogue part 2: deferred buf STG (off critical path) ----
#pragma unroll
        for (int nt = 0; nt < NT; ++nt) {
#pragma unroll
            for (int h2 = 0; h2 < 2; ++h2) {
                const int ll = mt * 16 + r4 + h2 * 8;
                const int co = g * COW + nt * 8 + cp2;
                base[((size_t)(co0h + co) * S + s_cur) * L + l0 + ll]     = osav[nt][h2][0];
                base[((size_t)(co0h + co + 1) * S + s_cur) * L + l0 + ll] = osav[nt][h2][1];
            }
        }

        cluster_sync();                       // DSMEM A[pcur] visible to sibling
    }
}

// ---------------------------------------------------------------------------
// Transpose [P, A, B] -> [P, B, A]
// ---------------------------------------------------------------------------
__global__ void transpose_kernel(const float* __restrict__ in,
                                 float* __restrict__ out, int A, int B)
{
    __shared__ float tile[32][33];
    const size_t p = blockIdx.z;
    const int b0 = blockIdx.x * 32;
    const int a0 = blockIdx.y * 32;
    const int tx = threadIdx.x, ty = threadIdx.y;
    const float* ip = in  + p * (size_t)A * B;
    float*       op = out + p * (size_t)A * B;
#pragma unroll
    for (int i = ty; i < 32; i += 8)
        tile[i][tx] = ip[(size_t)(a0+i)*B + (b0+tx)];
    __syncthreads();
#pragma unroll
    for (int i = ty; i < 32; i += 8)
        op[(size_t)(b0+i)*A + (a0+tx)] = tile[tx][i];
}

// Vertical: [B,C,S=H=128,L=W=256], M=32 (8 tiles). Horizontal: S=256,L=128, M=16.
#define PASSV pass_kernel<128,256,32>
#define PASSH pass_kernel<256,128,16>

static constexpr int SMEM_V = 2*(40*136*2) + KS*64*136*2 + 64*36*4;  // 187648
static constexpr int SMEM_H = 2*(24*136*2) + KS*64*136*2 + 64*20*4;  // 174848

extern "C" void kernel_launch(void* const* d_in, const int* in_sizes, int n_in,
                              void* d_out, int out_size)
{
    const float* x    = (const float*)d_in[0];
    const float* w_ud = (const float*)d_in[1];
    const float* w_du = (const float*)d_in[2];
    const float* w_lr = (const float*)d_in[3];
    const float* w_rl = (const float*)d_in[4];
    float* buf = (float*)d_out;

    float* tbuf = nullptr;
    cudaGetSymbolAddress((void**)&tbuf, g_tmp);
    unsigned* flags = nullptr;
    cudaGetSymbolAddress((void**)&flags, g_flags);

    cudaFuncSetAttribute(PASSV, cudaFuncAttributeMaxDynamicSharedMemorySize, SMEM_V);
    cudaFuncSetAttribute(PASSH, cudaFuncAttributeMaxDynamicSharedMemorySize, SMEM_H);

    cudaMemsetAsync(flags, 0, 4 * BATCH * 8 * 2 * 8 * sizeof(unsigned), 0);
    cudaMemcpyAsync(buf, x, (size_t)NTOT * sizeof(float),
                    cudaMemcpyDeviceToDevice, 0);

    const unsigned PSTRIDE = BATCH * 8 * 2 * 8;

    dim3 g(2, 8, BATCH);   // 128 CTAs = 64 clusters of 2, all resident
    PASSV<<<g, 256, SMEM_V>>>(buf, w_ud, flags + 0*PSTRIDE, 0);
    PASSV<<<g, 256, SMEM_V>>>(buf, w_du, flags + 1*PSTRIDE, 1);

    transpose_kernel<<<dim3(WW/32, HH/32, BATCH*CCH), dim3(32,8)>>>(buf, tbuf, HH, WW);

    PASSH<<<g, 256, SMEM_H>>>(tbuf, w_lr, flags + 2*PSTRIDE, 0);
    PASSH<<<g, 256, SMEM_H>>>(tbuf, w_rl, flags + 3*PSTRIDE, 1);

    transpose_kernel<<<dim3(HH/32, WW/32, BATCH*CCH), dim3(32,8)>>>(tbuf, buf, WW, HH);
}